// round 5
// baseline (speedup 1.0000x reference)
#include <cuda_runtime.h>

#define BB   2
#define C    32
#define H    192
#define W    192
#define HP   194
#define WP   194
#define OC   64
#define KK   288           // C * 9
#define GPX  64            // pixels per group
#define PITCH 292          // xo row pitch in floats (mult of 4; conflict-free)
#define NGPB 8             // groups per block
#define NBLK 144           // 144 * 8 * 64 = 73728 pixels

__device__ float g_xp[BB * HP * WP * C];   // padded NHWC input

// ---------------------------------------------------------------------------
// k_pad: NCHW -> padded NHWC via smem tile (coalesced read AND write)
// ---------------------------------------------------------------------------
__global__ void k_pad(const float* __restrict__ x) {
    __shared__ float sm[32][33];
    int bid = blockIdx.x;               // 2*192*6 = 2304
    int j0 = (bid % 6) * 32;
    int t = bid / 6;
    int i = t % H;
    int b = t / H;
    int tx = threadIdx.x, ty = threadIdx.y;   // (32, 8)
#pragma unroll
    for (int cc = 0; cc < 4; cc++) {
        int c = ty * 4 + cc;
        sm[c][tx] = x[((b * C + c) * H + i) * W + j0 + tx];
    }
    __syncthreads();
#pragma unroll
    for (int jj = 0; jj < 4; jj++) {
        int j = ty * 4 + jj;
        g_xp[((b * HP + i + 1) * WP + (j0 + j + 1)) * C + tx] = sm[tx][j];
    }
}

// ---------------------------------------------------------------------------
// k_border: zero the 1-pixel border of g_xp
// ---------------------------------------------------------------------------
__global__ void k_border() {
    int t = blockIdx.x * blockDim.x + threadIdx.x;
    if (t >= BB * 772 * 32) return;
    int c = t % 32;
    int cell = (t / 32) % 772;
    int b = t / (32 * 772);
    int i, j;
    if (cell < 194)      { i = 0;   j = cell; }
    else if (cell < 388) { i = 193; j = cell - 194; }
    else if (cell < 580) { i = cell - 388 + 1; j = 0; }
    else                 { i = cell - 580 + 1; j = 193; }
    g_xp[((b * HP + i) * WP + j) * C + c] = 0.f;
}

// ---------------------------------------------------------------------------
// helpers
// ---------------------------------------------------------------------------
__device__ __forceinline__ unsigned long long pack2(float v) {
    unsigned long long r;
    asm("mov.b64 %0, {%1, %1};" : "=l"(r) : "f"(v));
    return r;
}
__device__ __forceinline__ void fma2(unsigned long long& acc,
                                     unsigned long long a, unsigned long long b) {
    asm("fma.rn.f32x2 %0, %1, %2, %0;" : "+l"(acc) : "l"(a), "l"(b));
}
__device__ __forceinline__ void dim_(float v, int* idx, float* g) {
    float fl = floorf(v);
    float vc = fminf(fmaxf(v, 0.f), 193.f);
    float a0 = fminf(fmaxf(fl, 0.f), 193.f);
    float a1 = fminf(fmaxf(fl + 1.f, 0.f), 193.f);
    g[0] = 1.f + (a0 - vc);
    g[1] = 1.f - (a1 - vc);
    idx[0] = (int)a0;
    idx[1] = (int)a1;
}

// ---------------------------------------------------------------------------
// producer: gather one 64-px group's x_offset into xo (4 warps x 16 px)
// Phase A: batched A-map partials (high MLP) + interleaved shfl reductions.
// Phase B: bilinear gather per pixel (unroll 2 for ILP).
// ---------------------------------------------------------------------------
__device__ __forceinline__ void produce(int grp, float* xo, int pwid, int lane,
                                        const float* pw, float bias) {
    int b = grp / 576;
    int r = grp - b * 576;
    int i = r / 3;
    int j0 = (r - (r / 3) * 3) * GPX;
    const float* xpb = g_xp + (size_t)b * HP * WP * C + lane;   // lane = channel

    // ---- phase A: A-map for 16 pixels ----
    float Av[16];
#pragma unroll
    for (int pp = 0; pp < 16; pp++) {
        int j = j0 + pwid * 16 + pp;
        const float* base = xpb + (i * WP + j) * C;
        float s = 0.f;
#pragma unroll
        for (int n = 0; n < 9; n++) {
            int ki = n / 3, kj = n % 3;
            s = fmaf(base[(ki * WP + kj) * C], pw[n], s);
        }
        Av[pp] = s;
    }
#pragma unroll
    for (int off = 16; off; off >>= 1) {
#pragma unroll
        for (int pp = 0; pp < 16; pp++)
            Av[pp] += __shfl_xor_sync(0xffffffffu, Av[pp], off);
    }

    // ---- phase B: bilinear gather ----
#pragma unroll 2
    for (int pp = 0; pp < 16; pp++) {
        int pxl = pwid * 16 + pp;
        int j = j0 + pxl;
        float A = Av[pp] + bias;
        float fi = (float)(i + 1), fj = (float)(j + 1);
        int ro[6], co[6];
        float gxv[6], gyv[6];
        dim_(fi - A, ro + 0, gxv + 0);
        ro[2] = i + 1; gxv[2] = 1.f; ro[3] = i + 1; gxv[3] = 0.f;
        dim_(fi + A, ro + 4, gxv + 4);
        dim_(fj - A, co + 0, gyv + 0);
        co[2] = j + 1; gyv[2] = 1.f; co[3] = j + 1; gyv[3] = 0.f;
        dim_(fj + A, co + 4, gyv + 4);
        int rb_[6], cb_[6];
#pragma unroll
        for (int k = 0; k < 6; k++) { rb_[k] = ro[k] * (WP * C); cb_[k] = co[k] * C; }

        float* dst = xo + pxl * PITCH + lane * 9;   // k = c*9 + n
#pragma unroll
        for (int dxi = 0; dxi < 3; dxi++) {
#pragma unroll
            for (int dyi = 0; dyi < 3; dyi++) {
                int ra = rb_[2 * dxi], rbb = rb_[2 * dxi + 1];
                int ca = cb_[2 * dyi], cbb = cb_[2 * dyi + 1];
                float v00 = xpb[ra + ca],  v01 = xpb[ra + cbb];
                float v10 = xpb[rbb + ca], v11 = xpb[rbb + cbb];
                float ga0 = gxv[2 * dxi], ga1 = gxv[2 * dxi + 1];
                float gb0 = gyv[2 * dyi], gb1 = gyv[2 * dyi + 1];
                float xov = ga0 * (gb0 * v00 + gb1 * v01)
                          + ga1 * (gb0 * v10 + gb1 * v11);
                dst[dxi * 3 + dyi] = xov;
            }
        }
    }
}

// ---------------------------------------------------------------------------
// consumer: warp wid (0-7) -> output pairs [4*wid, 4*wid+4), lane = pixel
// (lane and lane+32), f32x2 over output pairs.
// ---------------------------------------------------------------------------
__device__ __forceinline__ void consume(int grp, const float* xo, const float2* wq,
                                        int wid, int lane, float* __restrict__ out) {
    unsigned long long acc0[4], acc1[4];
#pragma unroll
    for (int t = 0; t < 4; t++) { acc0[t] = 0ull; acc1[t] = 0ull; }

    const float4* x40 = (const float4*)xo + lane * (PITCH / 4);
    const float4* x41 = x40 + 32 * (PITCH / 4);
    const ulonglong2* wq2 = (const ulonglong2*)wq;   // 144 per o2
    int ob = wid * 4;
    const ulonglong2* wb0 = wq2 + (size_t)(ob + 0) * 144;
    const ulonglong2* wb1 = wq2 + (size_t)(ob + 1) * 144;
    const ulonglong2* wb2 = wq2 + (size_t)(ob + 2) * 144;
    const ulonglong2* wb3 = wq2 + (size_t)(ob + 3) * 144;

#pragma unroll 4
    for (int kq = 0; kq < KK / 4; kq++) {
        float4 v0 = x40[kq];
        float4 v1 = x41[kq];
        unsigned long long a0 = pack2(v0.x), b0 = pack2(v0.y),
                           c0 = pack2(v0.z), d0 = pack2(v0.w);
        unsigned long long a1 = pack2(v1.x), b1 = pack2(v1.y),
                           c1 = pack2(v1.z), d1 = pack2(v1.w);

        ulonglong2 wA, wB;
        wA = wb0[2 * kq]; wB = wb0[2 * kq + 1];
        fma2(acc0[0], a0, wA.x); fma2(acc0[0], b0, wA.y);
        fma2(acc0[0], c0, wB.x); fma2(acc0[0], d0, wB.y);
        fma2(acc1[0], a1, wA.x); fma2(acc1[0], b1, wA.y);
        fma2(acc1[0], c1, wB.x); fma2(acc1[0], d1, wB.y);
        wA = wb1[2 * kq]; wB = wb1[2 * kq + 1];
        fma2(acc0[1], a0, wA.x); fma2(acc0[1], b0, wA.y);
        fma2(acc0[1], c0, wB.x); fma2(acc0[1], d0, wB.y);
        fma2(acc1[1], a1, wA.x); fma2(acc1[1], b1, wA.y);
        fma2(acc1[1], c1, wB.x); fma2(acc1[1], d1, wB.y);
        wA = wb2[2 * kq]; wB = wb2[2 * kq + 1];
        fma2(acc0[2], a0, wA.x); fma2(acc0[2], b0, wA.y);
        fma2(acc0[2], c0, wB.x); fma2(acc0[2], d0, wB.y);
        fma2(acc1[2], a1, wA.x); fma2(acc1[2], b1, wA.y);
        fma2(acc1[2], c1, wB.x); fma2(acc1[2], d1, wB.y);
        wA = wb3[2 * kq]; wB = wb3[2 * kq + 1];
        fma2(acc0[3], a0, wA.x); fma2(acc0[3], b0, wA.y);
        fma2(acc0[3], c0, wB.x); fma2(acc0[3], d0, wB.y);
        fma2(acc1[3], a1, wA.x); fma2(acc1[3], b1, wA.y);
        fma2(acc1[3], c1, wB.x); fma2(acc1[3], d1, wB.y);
    }

    int b = grp / 576;
    int r = grp - b * 576;
    int i = r / 3;
    int j0 = (r - (r / 3) * 3) * GPX;
    size_t base = (size_t)b * OC * H * W + (size_t)i * W + j0;
#pragma unroll
    for (int t = 0; t < 4; t++) {
        float2 r0 = *(float2*)&acc0[t];
        float2 r1 = *(float2*)&acc1[t];
        int o = (ob + t) * 2;
        out[base + (size_t)o * (H * W) + lane] = r0.x;
        out[base + (size_t)(o + 1) * (H * W) + lane] = r0.y;
        out[base + (size_t)o * (H * W) + 32 + lane] = r1.x;
        out[base + (size_t)(o + 1) * (H * W) + 32 + lane] = r1.y;
    }
}

// ---------------------------------------------------------------------------
// k_main: 144 blocks x 8 groups. 384 threads: warps 0-7 consumers (2/SMSP),
// warps 8-11 producers (1/SMSP). double-buffered xo, weights loaded once.
// ---------------------------------------------------------------------------
__global__ __launch_bounds__(384, 1) void k_main(const float* __restrict__ convw,
                                                 const float* __restrict__ p1w,
                                                 const float* __restrict__ p1b,
                                                 float* __restrict__ out) {
    extern __shared__ char smem[];
    float2* wq = (float2*)smem;                      // [32][288] float2 = 73728 B
    float* xo0 = (float*)(smem + 32 * KK * 8);
    float* xo1 = xo0 + GPX * PITCH;

    int tid = threadIdx.x, wid = tid >> 5, lane = tid & 31;

    // weights -> smem: wq[o2*288 + k] = (w[2*o2][k], w[2*o2+1][k])
    for (int p = tid; p < 32 * KK; p += 384) {
        int o2 = p / KK, k = p - o2 * KK;
        wq[p] = make_float2(convw[(2 * o2) * KK + k],
                            convw[(2 * o2 + 1) * KK + k]);
    }

    float pw[9];
#pragma unroll
    for (int n = 0; n < 9; n++) pw[n] = p1w[lane * 9 + n];
    float bias = p1b[0];

    __syncthreads();

    bool is_cons = wid < 8;
    for (int it = 0; it <= NGPB; it++) {
        if (it < NGPB && !is_cons)
            produce(blockIdx.x * NGPB + it, (it & 1) ? xo1 : xo0,
                    wid - 8, lane, pw, bias);
        if (it > 0 && is_cons)
            consume(blockIdx.x * NGPB + it - 1, ((it - 1) & 1) ? xo1 : xo0,
                    wq, wid, lane, out);
        __syncthreads();
    }
}

// ---------------------------------------------------------------------------
extern "C" void kernel_launch(void* const* d_in, const int* in_sizes, int n_in,
                              void* d_out, int out_size) {
    const float *x = nullptr, *convw = nullptr, *p1w = nullptr, *p1b = nullptr;
    for (int i = 0; i < n_in; i++) {
        switch (in_sizes[i]) {
            case BB * C * H * W: x = (const float*)d_in[i]; break;     // 2359296
            case OC * C * 9:     convw = (const float*)d_in[i]; break; // 18432
            case C * 9:          p1w = (const float*)d_in[i]; break;   // 288
            case 1:              p1b = (const float*)d_in[i]; break;
            default: break;   // p_conv_w / p_conv_b unused
        }
    }
    float* out = (float*)d_out;

    dim3 tb(32, 8);
    k_pad<<<BB * H * (W / 32), tb>>>(x);
    int btot = BB * 772 * 32;
    k_border<<<(btot + 255) / 256, 256>>>();

    const int smem_bytes = 32 * KK * 8 + 2 * GPX * PITCH * 4;   // 223232
    cudaFuncSetAttribute(k_main, cudaFuncAttributeMaxDynamicSharedMemorySize,
                         smem_bytes);

    k_main<<<NBLK, 384, smem_bytes>>>(convw, p1w, p1b, out);
}

// round 6
// speedup vs baseline: 1.0059x; 1.0059x over previous
#include <cuda_runtime.h>

#define BB   2
#define C    32
#define H    192
#define W    192
#define HP   194
#define WP   194
#define OC   64
#define KK   288           // C * 9
#define GPX  64            // pixels per group
#define PITCH 292          // xo row pitch in floats (mult of 4; conflict-free)
#define NGPB 8             // groups per block
#define NBLK 144           // 144 * 8 * 64 = 73728 pixels

__device__ float g_xp[BB * HP * WP * C];   // padded NHWC input

// ---------------------------------------------------------------------------
// k_pad: NCHW -> padded NHWC via smem tile (coalesced read AND write)
// ---------------------------------------------------------------------------
__global__ void k_pad(const float* __restrict__ x) {
    __shared__ float sm[32][33];
    int bid = blockIdx.x;               // 2*192*6 = 2304
    int j0 = (bid % 6) * 32;
    int t = bid / 6;
    int i = t % H;
    int b = t / H;
    int tx = threadIdx.x, ty = threadIdx.y;   // (32, 8)
#pragma unroll
    for (int cc = 0; cc < 4; cc++) {
        int c = ty * 4 + cc;
        sm[c][tx] = x[((b * C + c) * H + i) * W + j0 + tx];
    }
    __syncthreads();
#pragma unroll
    for (int jj = 0; jj < 4; jj++) {
        int j = ty * 4 + jj;
        g_xp[((b * HP + i + 1) * WP + (j0 + j + 1)) * C + tx] = sm[tx][j];
    }
}

// ---------------------------------------------------------------------------
// k_border: zero the 1-pixel border of g_xp
// ---------------------------------------------------------------------------
__global__ void k_border() {
    int t = blockIdx.x * blockDim.x + threadIdx.x;
    if (t >= BB * 772 * 32) return;
    int c = t % 32;
    int cell = (t / 32) % 772;
    int b = t / (32 * 772);
    int i, j;
    if (cell < 194)      { i = 0;   j = cell; }
    else if (cell < 388) { i = 193; j = cell - 194; }
    else if (cell < 580) { i = cell - 388 + 1; j = 0; }
    else                 { i = cell - 580 + 1; j = 193; }
    g_xp[((b * HP + i) * WP + j) * C + c] = 0.f;
}

// ---------------------------------------------------------------------------
// helpers
// ---------------------------------------------------------------------------
__device__ __forceinline__ unsigned long long pack2(float v) {
    unsigned long long r;
    asm("mov.b64 %0, {%1, %1};" : "=l"(r) : "f"(v));
    return r;
}
__device__ __forceinline__ void fma2(unsigned long long& acc,
                                     unsigned long long a, unsigned long long b) {
    asm("fma.rn.f32x2 %0, %1, %2, %0;" : "+l"(acc) : "l"(a), "l"(b));
}
__device__ __forceinline__ void dim_(float v, int* idx, float* g) {
    float fl = floorf(v);
    float vc = fminf(fmaxf(v, 0.f), 193.f);
    float a0 = fminf(fmaxf(fl, 0.f), 193.f);
    float a1 = fminf(fmaxf(fl + 1.f, 0.f), 193.f);
    g[0] = 1.f + (a0 - vc);
    g[1] = 1.f - (a1 - vc);
    idx[0] = (int)a0;
    idx[1] = (int)a1;
}

// ---------------------------------------------------------------------------
// producer: gather one 64-px group's x_offset into xo (4 warps x 16 px)
// Phase A: batched A-map partials (high MLP) + interleaved shfl reductions.
// Phase B: bilinear gather per pixel (unroll 2 for ILP).
// ---------------------------------------------------------------------------
__device__ __forceinline__ void produce(int grp, float* xo, int pwid, int lane,
                                        const float* pw, float bias) {
    int b = grp / 576;
    int r = grp - b * 576;
    int i = r / 3;
    int j0 = (r - (r / 3) * 3) * GPX;
    const float* xpb = g_xp + (size_t)b * HP * WP * C + lane;   // lane = channel

    // ---- phase A: A-map for 16 pixels ----
    float Av[16];
#pragma unroll
    for (int pp = 0; pp < 16; pp++) {
        int j = j0 + pwid * 16 + pp;
        const float* base = xpb + (i * WP + j) * C;
        float s = 0.f;
#pragma unroll
        for (int n = 0; n < 9; n++) {
            int ki = n / 3, kj = n % 3;
            s = fmaf(base[(ki * WP + kj) * C], pw[n], s);
        }
        Av[pp] = s;
    }
#pragma unroll
    for (int off = 16; off; off >>= 1) {
#pragma unroll
        for (int pp = 0; pp < 16; pp++)
            Av[pp] += __shfl_xor_sync(0xffffffffu, Av[pp], off);
    }

    // ---- phase B: bilinear gather ----
#pragma unroll 2
    for (int pp = 0; pp < 16; pp++) {
        int pxl = pwid * 16 + pp;
        int j = j0 + pxl;
        float A = Av[pp] + bias;
        float fi = (float)(i + 1), fj = (float)(j + 1);
        int ro[6], co[6];
        float gxv[6], gyv[6];
        dim_(fi - A, ro + 0, gxv + 0);
        ro[2] = i + 1; gxv[2] = 1.f; ro[3] = i + 1; gxv[3] = 0.f;
        dim_(fi + A, ro + 4, gxv + 4);
        dim_(fj - A, co + 0, gyv + 0);
        co[2] = j + 1; gyv[2] = 1.f; co[3] = j + 1; gyv[3] = 0.f;
        dim_(fj + A, co + 4, gyv + 4);
        int rb_[6], cb_[6];
#pragma unroll
        for (int k = 0; k < 6; k++) { rb_[k] = ro[k] * (WP * C); cb_[k] = co[k] * C; }

        float* dst = xo + pxl * PITCH + lane * 9;   // k = c*9 + n
#pragma unroll
        for (int dxi = 0; dxi < 3; dxi++) {
#pragma unroll
            for (int dyi = 0; dyi < 3; dyi++) {
                int ra = rb_[2 * dxi], rbb = rb_[2 * dxi + 1];
                int ca = cb_[2 * dyi], cbb = cb_[2 * dyi + 1];
                float v00 = xpb[ra + ca],  v01 = xpb[ra + cbb];
                float v10 = xpb[rbb + ca], v11 = xpb[rbb + cbb];
                float ga0 = gxv[2 * dxi], ga1 = gxv[2 * dxi + 1];
                float gb0 = gyv[2 * dyi], gb1 = gyv[2 * dyi + 1];
                float xov = ga0 * (gb0 * v00 + gb1 * v01)
                          + ga1 * (gb0 * v10 + gb1 * v11);
                dst[dxi * 3 + dyi] = xov;
            }
        }
    }
}

// ---------------------------------------------------------------------------
// consumer: warp wid (0-7) -> output pairs [4*wid, 4*wid+4), lane = pixel
// (lane and lane+32), f32x2 over output pairs.
// ---------------------------------------------------------------------------
__device__ __forceinline__ void consume(int grp, const float* xo, const float2* wq,
                                        int wid, int lane, float* __restrict__ out) {
    unsigned long long acc0[4], acc1[4];
#pragma unroll
    for (int t = 0; t < 4; t++) { acc0[t] = 0ull; acc1[t] = 0ull; }

    const float4* x40 = (const float4*)xo + lane * (PITCH / 4);
    const float4* x41 = x40 + 32 * (PITCH / 4);
    const ulonglong2* wq2 = (const ulonglong2*)wq;   // 144 per o2
    int ob = wid * 4;
    const ulonglong2* wb0 = wq2 + (size_t)(ob + 0) * 144;
    const ulonglong2* wb1 = wq2 + (size_t)(ob + 1) * 144;
    const ulonglong2* wb2 = wq2 + (size_t)(ob + 2) * 144;
    const ulonglong2* wb3 = wq2 + (size_t)(ob + 3) * 144;

#pragma unroll 4
    for (int kq = 0; kq < KK / 4; kq++) {
        float4 v0 = x40[kq];
        float4 v1 = x41[kq];
        unsigned long long a0 = pack2(v0.x), b0 = pack2(v0.y),
                           c0 = pack2(v0.z), d0 = pack2(v0.w);
        unsigned long long a1 = pack2(v1.x), b1 = pack2(v1.y),
                           c1 = pack2(v1.z), d1 = pack2(v1.w);

        ulonglong2 wA, wB;
        wA = wb0[2 * kq]; wB = wb0[2 * kq + 1];
        fma2(acc0[0], a0, wA.x); fma2(acc0[0], b0, wA.y);
        fma2(acc0[0], c0, wB.x); fma2(acc0[0], d0, wB.y);
        fma2(acc1[0], a1, wA.x); fma2(acc1[0], b1, wA.y);
        fma2(acc1[0], c1, wB.x); fma2(acc1[0], d1, wB.y);
        wA = wb1[2 * kq]; wB = wb1[2 * kq + 1];
        fma2(acc0[1], a0, wA.x); fma2(acc0[1], b0, wA.y);
        fma2(acc0[1], c0, wB.x); fma2(acc0[1], d0, wB.y);
        fma2(acc1[1], a1, wA.x); fma2(acc1[1], b1, wA.y);
        fma2(acc1[1], c1, wB.x); fma2(acc1[1], d1, wB.y);
        wA = wb2[2 * kq]; wB = wb2[2 * kq + 1];
        fma2(acc0[2], a0, wA.x); fma2(acc0[2], b0, wA.y);
        fma2(acc0[2], c0, wB.x); fma2(acc0[2], d0, wB.y);
        fma2(acc1[2], a1, wA.x); fma2(acc1[2], b1, wA.y);
        fma2(acc1[2], c1, wB.x); fma2(acc1[2], d1, wB.y);
        wA = wb3[2 * kq]; wB = wb3[2 * kq + 1];
        fma2(acc0[3], a0, wA.x); fma2(acc0[3], b0, wA.y);
        fma2(acc0[3], c0, wB.x); fma2(acc0[3], d0, wB.y);
        fma2(acc1[3], a1, wA.x); fma2(acc1[3], b1, wA.y);
        fma2(acc1[3], c1, wB.x); fma2(acc1[3], d1, wB.y);
    }

    int b = grp / 576;
    int r = grp - b * 576;
    int i = r / 3;
    int j0 = (r - (r / 3) * 3) * GPX;
    size_t base = (size_t)b * OC * H * W + (size_t)i * W + j0;
#pragma unroll
    for (int t = 0; t < 4; t++) {
        float2 r0 = *(float2*)&acc0[t];
        float2 r1 = *(float2*)&acc1[t];
        int o = (ob + t) * 2;
        out[base + (size_t)o * (H * W) + lane] = r0.x;
        out[base + (size_t)(o + 1) * (H * W) + lane] = r0.y;
        out[base + (size_t)o * (H * W) + 32 + lane] = r1.x;
        out[base + (size_t)(o + 1) * (H * W) + 32 + lane] = r1.y;
    }
}

// ---------------------------------------------------------------------------
// k_main: 144 blocks x 8 groups. 384 threads: warps 0-7 consumers (2/SMSP),
// warps 8-11 producers (1/SMSP). double-buffered xo, weights loaded once.
// ---------------------------------------------------------------------------
__global__ __launch_bounds__(384, 1) void k_main(const float* __restrict__ convw,
                                                 const float* __restrict__ p1w,
                                                 const float* __restrict__ p1b,
                                                 float* __restrict__ out) {
    extern __shared__ char smem[];
    float2* wq = (float2*)smem;                      // [32][288] float2 = 73728 B
    float* xo0 = (float*)(smem + 32 * KK * 8);
    float* xo1 = xo0 + GPX * PITCH;

    int tid = threadIdx.x, wid = tid >> 5, lane = tid & 31;

    // weights -> smem: wq[o2*288 + k] = (w[2*o2][k], w[2*o2+1][k])
    for (int p = tid; p < 32 * KK; p += 384) {
        int o2 = p / KK, k = p - o2 * KK;
        wq[p] = make_float2(convw[(2 * o2) * KK + k],
                            convw[(2 * o2 + 1) * KK + k]);
    }

    float pw[9];
#pragma unroll
    for (int n = 0; n < 9; n++) pw[n] = p1w[lane * 9 + n];
    float bias = p1b[0];

    __syncthreads();

    bool is_cons = wid < 8;
    for (int it = 0; it <= NGPB; it++) {
        if (it < NGPB && !is_cons)
            produce(blockIdx.x * NGPB + it, (it & 1) ? xo1 : xo0,
                    wid - 8, lane, pw, bias);
        if (it > 0 && is_cons)
            consume(blockIdx.x * NGPB + it - 1, ((it - 1) & 1) ? xo1 : xo0,
                    wq, wid, lane, out);
        __syncthreads();
    }
}

// ---------------------------------------------------------------------------
extern "C" void kernel_launch(void* const* d_in, const int* in_sizes, int n_in,
                              void* d_out, int out_size) {
    const float *x = nullptr, *convw = nullptr, *p1w = nullptr, *p1b = nullptr;
    for (int i = 0; i < n_in; i++) {
        switch (in_sizes[i]) {
            case BB * C * H * W: x = (const float*)d_in[i]; break;     // 2359296
            case OC * C * 9:     convw = (const float*)d_in[i]; break; // 18432
            case C * 9:          p1w = (const float*)d_in[i]; break;   // 288
            case 1:              p1b = (const float*)d_in[i]; break;
            default: break;   // p_conv_w / p_conv_b unused
        }
    }
    float* out = (float*)d_out;

    dim3 tb(32, 8);
    k_pad<<<BB * H * (W / 32), tb>>>(x);
    int btot = BB * 772 * 32;
    k_border<<<(btot + 255) / 256, 256>>>();

    const int smem_bytes = 32 * KK * 8 + 2 * GPX * PITCH * 4;   // 223232
    cudaFuncSetAttribute(k_main, cudaFuncAttributeMaxDynamicSharedMemorySize,
                         smem_bytes);

    k_main<<<NBLK, 384, smem_bytes>>>(convw, p1w, p1b, out);
}